// round 17
// baseline (speedup 1.0000x reference)
#include <cuda_runtime.h>

// Problem constants (match reference)
#define K_VOX 12000
#define T_PTS 35
#define F_IN  7
#define D_DIM 10
#define H_DIM 400
#define W_DIM 352
#define C_OUT_DIM 128
#define EPSVAL 1e-3f

// Fused grid: period-4 interleave, 3 zero-role + 1 compute-role blocks
// (best-measured ratio point: R12 fused = 118.8us).
#define NB_TOTAL 12000
#define N_ZERO_BLK 9000
#define ZERO_THREADS (N_ZERO_BLK * 256)

// Voxel-wise results staged here (fully overwritten each launch).
__device__ float g_vox[K_VOX * C_OUT_DIM];   // 6.1 MB

// ---- Blackwell packed-f32 helpers (fma.rn.f32x2: 2 FMAs / instruction) ----
__device__ __forceinline__ unsigned long long pack2(float lo, float hi) {
    unsigned long long r;
    asm("mov.b64 %0, {%1, %2};" : "=l"(r) : "f"(lo), "f"(hi));
    return r;
}
__device__ __forceinline__ unsigned long long fma2(
    unsigned long long a, unsigned long long b, unsigned long long c) {
    unsigned long long d;
    asm("fma.rn.f32x2 %0, %1, %2, %3;" : "=l"(d) : "l"(a), "l"(b), "l"(c));
    return d;
}
__device__ __forceinline__ unsigned long long add2(
    unsigned long long a, unsigned long long b) {
    unsigned long long d;
    asm("add.rn.f32x2 %0, %1, %2;" : "=l"(d) : "l"(a), "l"(b));
    return d;
}
__device__ __forceinline__ void unpack2(float& lo, float& hi,
                                        unsigned long long v) {
    asm("mov.b64 {%0, %1}, %2;" : "=f"(lo), "=f"(hi) : "l"(v));
}

// 16B vector reduction (sm_90+): one REDG op instead of four.
__device__ __forceinline__ void red_add_v4(float* dst, float4 v) {
    asm volatile("red.global.add.v4.f32 [%0], {%1, %2, %3, %4};"
                 :: "l"(dst), "f"(v.x), "f"(v.y), "f"(v.z), "f"(v.w)
                 : "memory");
}

// ---------------------------------------------------------------------------
// Fused kernel: zero the 720MB output AND compute voxel features concurrently
// as interleaved blocks of one grid. Stage-2 uses packed f32x2 FMAs to cut
// compute's issue-slot footprint ~25%.
// ---------------------------------------------------------------------------
__global__ __launch_bounds__(256) void fused_kernel(
    const float* __restrict__ feat,     // [K, T, F]
    const float* __restrict__ w1,       // [F, 16]
    const float* __restrict__ b1,
    const float* __restrict__ gamma1, const float* __restrict__ beta1,
    const float* __restrict__ mean1,  const float* __restrict__ var1,
    const float* __restrict__ w2,       // [32, 64]
    const float* __restrict__ b2,
    const float* __restrict__ gamma2, const float* __restrict__ beta2,
    const float* __restrict__ mean2,  const float* __restrict__ var2,
    float*       __restrict__ out,      // [1, D, H, W, 128] — zeroed here
    int n4)                             // out_size / 4 (float4 count)
{
    const int bid = blockIdx.x;
    const int tid = threadIdx.x;
    const int r = bid & 3;

    if (r < 3) {
        // ---------------- Zero role ----------------
        const int zid = (bid >> 2) * 3 + r;
        float4* o4 = (float4*)out;
        const float4 z = make_float4(0.f, 0.f, 0.f, 0.f);
        for (int i = zid * 256 + tid; i < n4; i += ZERO_THREADS) o4[i] = z;
        return;
    }

    // ---------------- Compute role ----------------
    const int cid = bid >> 2;                   // 0..2999
    const int g   = tid >> 6;                   // group 0..3 (one voxel each)
    const int v   = tid & 63;                   // output channel within group
    const int k   = cid * 4 + g;                // voxel id

    __shared__ float sw1[F_IN * 16];
    __shared__ float sb1[16], ss1[16], so1[16], spw1b[16];
    __shared__ float sfeat[4][T_PTS * F_IN];
    __shared__ int   smask[4][T_PTS];
    __shared__ __align__(16) float pw1s[4][T_PTS * 16];
    __shared__ float sagg1[4][16];

    // Block-invariant stage-1 params
    if (tid < F_IN * 16) sw1[tid] = w1[tid];
    if (tid < 16) {
        float s = gamma1[tid] * rsqrtf(var1[tid] + EPSVAL);
        float o = beta1[tid] - mean1[tid] * s;
        float bb = b1[tid];
        ss1[tid] = s; so1[tid] = o; sb1[tid] = bb;
        spw1b[tid] = fmaxf(bb, 0.f) * s + o;    // pw1 of a fully-masked point
    }

    // Per-thread stage-2 params (thread owns channels v and 64+v)
    const float s2v = gamma2[v] * rsqrtf(var2[v] + EPSVAL);
    const float o2v = beta2[v] - mean2[v] * s2v;
    const float b2v = b2[v];
    const float pw2b = fmaxf(b2v, 0.f) * s2v + o2v;   // pw2 of a masked point

    // Packed w2 column pairs for the per-point half (u = 2j, 2j+1).
    unsigned long long wp[8];
#pragma unroll
    for (int j = 0; j < 8; j++)
        wp[j] = pack2(__ldg(&w2[(2 * j) * 64 + v]),
                      __ldg(&w2[(2 * j + 1) * 64 + v]));

    // Load this group's point features
    for (int i = v; i < T_PTS * F_IN; i += 64)
        sfeat[g][i] = feat[k * (T_PTS * F_IN) + i];
    __syncthreads();

    // Mask: point valid iff max over its features != 0
    if (v < T_PTS) {
        float m = sfeat[g][v * F_IN];
#pragma unroll
        for (int f = 1; f < F_IN; f++) m = fmaxf(m, sfeat[g][v * F_IN + f]);
        smask[g][v] = (m != 0.f) ? 1 : 0;
    }
    __syncthreads();

    // Stage 1: pw1_eff[t][u] (masked rows take the constant pw1b[u])
    for (int e = v; e < T_PTS * 16; e += 64) {
        const int t = e >> 4, u = e & 15;
        float val;
        if (smask[g][t]) {
            float d = sb1[u];
#pragma unroll
            for (int f = 0; f < F_IN; f++)
                d = fmaf(sfeat[g][t * F_IN + f], sw1[f * 16 + u], d);
            val = fmaxf(d, 0.f) * ss1[u] + so1[u];
        } else {
            val = spw1b[u];
        }
        pw1s[g][e] = val;
    }
    __syncthreads();

    // agg1[u] = max over ALL t of pw1_eff (reference maxes pre-mask)
    if (v < 16) {
        float m = pw1s[g][v];
        for (int t = 1; t < T_PTS; t++) m = fmaxf(m, pw1s[g][t * 16 + v]);
        sagg1[g][v] = m;
    }
    __syncthreads();

    // Stage 2: agg-half dot once per voxel (L2-hot w2, no register array)
    float aggdot = 0.f;
#pragma unroll
    for (int j = 0; j < 16; j++)
        aggdot = fmaf(sagg1[g][j], __ldg(&w2[(16 + j) * 64 + v]), aggdot);
    const float base2 = b2v + aggdot;

    // Per-point dot with packed f32x2 FMAs (8 FFMA2 instead of 16 FFMA)
    float m2 = -3.4e38f;
    int anyInvalid = 0, anyValid = 0;
    for (int t = 0; t < T_PTS; t++) {
        if (smask[g][t]) {
            anyValid = 1;
            const ulonglong2* row = (const ulonglong2*)(pw1s[g] + t * 16);
            ulonglong2 q0 = row[0], q1 = row[1], q2 = row[2], q3 = row[3];
            unsigned long long a0 = 0ULL, a1 = 0ULL;
            a0 = fma2(q0.x, wp[0], a0);  a1 = fma2(q0.y, wp[1], a1);
            a0 = fma2(q1.x, wp[2], a0);  a1 = fma2(q1.y, wp[3], a1);
            a0 = fma2(q2.x, wp[4], a0);  a1 = fma2(q2.y, wp[5], a1);
            a0 = fma2(q3.x, wp[6], a0);  a1 = fma2(q3.y, wp[7], a1);
            const unsigned long long s = add2(a0, a1);
            float lo, hi; unpack2(lo, hi, s);
            const float d = (lo + hi) + base2;
            m2 = fmaxf(m2, fmaxf(d, 0.f) * s2v + o2v);
        } else {
            anyInvalid = 1;
        }
    }

    float outA, outB;
    if (!anyValid) {
        outA = 0.f; outB = 0.f;
    } else if (anyInvalid) {
        outA = fmaxf(m2, 0.f);                  // masked rows give 0 post-mask
        outB = fmaxf(fmaxf(m2, pw2b), 0.f);     // agg includes masked pw2b
    } else {
        outA = m2; outB = m2;
    }

    g_vox[k * C_OUT_DIM + v]      = outA;
    g_vox[k * C_OUT_DIM + 64 + v] = outB;
}

// ---------------------------------------------------------------------------
// Scatter: vectorized reductions (red.global.add.v4.f32) with MLP=2.
// Measured 6.1us in R16.
// ---------------------------------------------------------------------------
__global__ __launch_bounds__(256) void scatter_kernel(
    const int* __restrict__ coord,      // [K, 4]
    float*     __restrict__ out)
{
    const int i0 = blockIdx.x * 512 + threadIdx.x;   // two halves per block
    const int i1 = i0 + 256;

    const int k0 = i0 >> 5, c40 = i0 & 31;
    const int k1 = i1 >> 5, c41 = i1 & 31;

    // Issue all loads before any reduction (MLP).
    const int4 cc0 = __ldg(&((const int4*)coord)[k0]);
    const int4 cc1 = __ldg(&((const int4*)coord)[k1]);
    const float4 v0 = ((const float4*)(g_vox + k0 * C_OUT_DIM))[c40];
    const float4 v1 = ((const float4*)(g_vox + k1 * C_OUT_DIM))[c41];

    const int base0 =
        (((cc0.x * D_DIM + cc0.y) * H_DIM + cc0.z) * W_DIM + cc0.w) * C_OUT_DIM;
    const int base1 =
        (((cc1.x * D_DIM + cc1.y) * H_DIM + cc1.z) * W_DIM + cc1.w) * C_OUT_DIM;

    red_add_v4(out + base0 + c40 * 4, v0);
    red_add_v4(out + base1 + c41 * 4, v1);
}

// ---------------------------------------------------------------------------
extern "C" void kernel_launch(void* const* d_in, const int* in_sizes, int n_in,
                              void* d_out, int out_size) {
    const float* feat   = (const float*)d_in[0];
    const float* w1     = (const float*)d_in[1];
    const float* b1     = (const float*)d_in[2];
    const float* gamma1 = (const float*)d_in[3];
    const float* beta1  = (const float*)d_in[4];
    const float* mean1  = (const float*)d_in[5];
    const float* var1   = (const float*)d_in[6];
    const float* w2     = (const float*)d_in[7];
    const float* b2     = (const float*)d_in[8];
    const float* gamma2 = (const float*)d_in[9];
    const float* beta2  = (const float*)d_in[10];
    const float* mean2  = (const float*)d_in[11];
    const float* var2   = (const float*)d_in[12];
    const int*   coord  = (const int*)d_in[13];
    float* out = (float*)d_out;

    const int n4 = out_size / 4;
    fused_kernel<<<NB_TOTAL, 256>>>(feat, w1, b1, gamma1, beta1, mean1, var1,
                                    w2, b2, gamma2, beta2, mean2, var2,
                                    out, n4);
    scatter_kernel<<<(K_VOX * 32) / 512, 256>>>(coord, out);
}